// round 12
// baseline (speedup 1.0000x reference)
#include <cuda_runtime.h>

// FullAutoLSTM, GB300 sm_103a.
// Single persistent kernel: 128 fully independent CTAs, each owning 8 batch
// rows and running the entire 1024-step recurrence locally (h, c, y feedback
// all CTA-local in smem). Graph = 2 nodes -> no graph-upload allocation.
//
// B=1024, H=256, F=32 (24 auto feats + 8 recurrent y), O=8, Tw=Ta=512.
// Per-step z-GEMM: (8 x 288) @ (288 x 1024) per CTA, fp32 via fma.rn.f32x2.

#define B    1024
#define H    256
#define F    32
#define FA   24     // auto features (F - O)
#define O    8
#define TW   512
#define TA   512
#define TT   1024
#define K    288    // F + H
#define BT   8      // batch rows per CTA
#define NCTA (B / BT)       // 128
#define THREADS 256

typedef unsigned long long ull;

// Gate-interleaved repacked weights: g_Wr[k*1024 + j*4 + g],
// g = 0:i 1:f 2:g 3:o ; source col = g*256 + j.
__device__ float g_Wr[K * 4 * H];

__device__ __forceinline__ float fsig(float x)  { return 1.0f / (1.0f + __expf(-x)); }
__device__ __forceinline__ float ftanh(float x) { return 2.0f / (1.0f + __expf(-2.0f * x)) - 1.0f; }

__device__ __forceinline__ void fma2(ull& acc, ull a, ull b) {
    asm("fma.rn.f32x2 %0, %1, %2, %0;" : "+l"(acc) : "l"(a), "l"(b));
}
__device__ __forceinline__ float2 unpack2(ull v) {
    float2 r;
    asm("mov.b64 {%0, %1}, %2;" : "=f"(r.x), "=f"(r.y) : "l"(v));
    return r;
}

__global__ void repack_kernel(const float* __restrict__ W_ih,
                              const float* __restrict__ W_hh) {
    int i = blockIdx.x * blockDim.x + threadIdx.x;
    if (i >= K * 4 * H) return;
    int k = i >> 10;
    int c = i & 1023;
    int j = c >> 2;
    int g = c & 3;
    int col = g * H + j;
    g_Wr[i] = (k < F) ? W_ih[(size_t)k * (4 * H) + col]
                      : W_hh[(size_t)(k - F) * (4 * H) + col];
}

__global__ void __launch_bounds__(THREADS, 1)
lstm_main(const float* __restrict__ c0,
          const float* __restrict__ h0,
          const float* __restrict__ warm,    // (B, TW, F)
          const float* __restrict__ autoin,  // (B, TA, FA)
          const float* __restrict__ bias,    // (4H)
          const float* __restrict__ W_out,   // (H, O)
          const float* __restrict__ b_out,   // (O)
          float* __restrict__ out)           // (B, TT, O)
{
    // Activations duplicated per lane for f32x2: sxX[k][r] = {x, x}.
    // k in [0,F): input features (+ y feedback in [FA,F)); k in [F,K): h.
    __shared__ float2 sxX[K][BT];       // 18432 B
    __shared__ float  c_st[BT][H];      //  8192 B
    __shared__ float  swout[H * O];     //  8192 B
    __shared__ float  psum[BT * O][4];  //  1024 B

    const int t  = threadIdx.x;
    const int b0 = blockIdx.x * BT;

    // ---- one-time preload ----
    for (int i = t; i < H * O; i += THREADS) swout[i] = W_out[i];
#pragma unroll
    for (int r = 0; r < BT; r++) {
        float hv = h0[(size_t)(b0 + r) * H + t];
        sxX[F + t][r] = make_float2(hv, hv);
        c_st[r][t]    = c0[(size_t)(b0 + r) * H + t];
    }
    const float bi = bias[t];
    const float bf = bias[H + t];
    const float bg = bias[2 * H + t];
    const float bo = bias[3 * H + t];

    const ulonglong2* __restrict__ Wp =
        reinterpret_cast<const ulonglong2*>(g_Wr) + t;  // +k*256 per k row

    for (int s = 0; s < TT; s++) {
        // ---- stage x_s ----
        if (s < TW) {
            int k = t & 31, r = t >> 5;
            float v = warm[((size_t)(b0 + r) * TW + s) * F + k];
            sxX[k][r] = make_float2(v, v);
        } else if (t < FA * BT) {
            int r = t / FA, k = t - r * FA;
            float v = autoin[((size_t)(b0 + r) * TA + (s - TW)) * FA + k];
            sxX[k][r] = make_float2(v, v);
        }
        __syncthreads();  // S1: staging (and prev h/y writes) visible

        // ---- z GEMM: thread t owns all 4 gates of hidden unit j=t, rows 0..7
        // acc0[r] = {z_i[r], z_f[r]}, acc1[r] = {z_g[r], z_o[r]}
        ull acc0[BT], acc1[BT];
#pragma unroll
        for (int r = 0; r < BT; r++) { acc0[r] = 0ULL; acc1[r] = 0ULL; }

        const ull* __restrict__ xs = reinterpret_cast<const ull*>(sxX);
#pragma unroll 8
        for (int k = 0; k < K; k++) {
            ulonglong2 w = Wp[k * 256];  // {w_i,w_f},{w_g,w_o} for unit t
#pragma unroll
            for (int r = 0; r < BT; r++) {
                ull xx = xs[k * BT + r];  // {x, x}
                fma2(acc0[r], xx, w.x);
                fma2(acc1[r], xx, w.y);
            }
        }

        // ---- gates + cell update (registers + exclusive c column) ----
        float hreg[BT];
#pragma unroll
        for (int r = 0; r < BT; r++) {
            float2 zif = unpack2(acc0[r]);
            float2 zgo = unpack2(acc1[r]);
            float ig = fsig(zif.x + bi);
            float fg = fsig(zif.y + bf);
            float gg = ftanh(zgo.x + bg);
            float og = fsig(zgo.y + bo);
            float c  = fmaf(fg, c_st[r][t], ig * gg);
            c_st[r][t] = c;
            hreg[r] = og * ftanh(c);
        }
        __syncthreads();  // S2: all GEMM reads of sxX complete

#pragma unroll
        for (int r = 0; r < BT; r++)
            sxX[F + t][r] = make_float2(hreg[r], hreg[r]);
        __syncthreads();  // S3: new h visible

        // ---- y_s = h_s @ W_out + b_out (partials over 4 j-chunks) ----
        {
            int combo = t & 63;           // (r, o)
            int part  = t >> 6;           // 0..3 -> j chunk of 64
            int r = combo >> 3, o = combo & 7;
            int jb = part * 64;
            float a0 = 0.f, a1 = 0.f, a2 = 0.f, a3 = 0.f;
#pragma unroll 16
            for (int jj = 0; jj < 64; jj += 4) {
                a0 = fmaf(sxX[F + jb + jj + 0][r].x, swout[(jb + jj + 0) * O + o], a0);
                a1 = fmaf(sxX[F + jb + jj + 1][r].x, swout[(jb + jj + 1) * O + o], a1);
                a2 = fmaf(sxX[F + jb + jj + 2][r].x, swout[(jb + jj + 2) * O + o], a2);
                a3 = fmaf(sxX[F + jb + jj + 3][r].x, swout[(jb + jj + 3) * O + o], a3);
            }
            psum[combo][part] = (a0 + a1) + (a2 + a3);
        }
        __syncthreads();  // S4: partials visible

        if (t < BT * O) {
            int r = t >> 3, o = t & 7;
            float y = b_out[o] + ((psum[t][0] + psum[t][1]) +
                                  (psum[t][2] + psum[t][3]));
            out[((size_t)(b0 + r) * TT + s) * O + o] = y;
            // Feedback slots only needed entering the auto phase; skipping
            // earlier avoids a write race with warm staging of step s+1.
            if (s >= TW - 1)
                sxX[FA + o][r] = make_float2(y, y);
        }
        // next-iteration staging writes disjoint slots; S1 orders before GEMM
    }
}

extern "C" void kernel_launch(void* const* d_in, const int* in_sizes, int n_in,
                              void* d_out, int out_size) {
    const float* c0     = (const float*)d_in[0];
    const float* h0     = (const float*)d_in[1];
    const float* warm   = (const float*)d_in[2];
    const float* autoin = (const float*)d_in[3];
    const float* W_ih   = (const float*)d_in[4];
    const float* W_hh   = (const float*)d_in[5];
    const float* bias   = (const float*)d_in[6];
    const float* W_out  = (const float*)d_in[7];
    const float* b_out  = (const float*)d_in[8];
    float* out = (float*)d_out;

    repack_kernel<<<(K * 4 * H + 255) / 256, 256>>>(W_ih, W_hh);
    lstm_main<<<NCTA, THREADS>>>(c0, h0, warm, autoin, bias, W_out, b_out, out);
}